// round 11
// baseline (speedup 1.0000x reference)
#include <cuda_runtime.h>
#include <cuda_fp16.h>
#include <cstdint>

#define B_SZ  4096
#define IN_F  256
#define OUT_F 256
#define HYP   128
#define BM    128
#define BN    64

// ---------------- device scratch (allocation-free rule) ----------------
__device__ __align__(256) float  g_hgT[HYP * B_SZ];                    // [h][b] fp32
__device__ __align__(256) __half g_hb16[B_SZ * HYP];                   // [b][h]
__device__ __align__(256) __half g_x16[B_SZ * IN_F];                   // [b][i]
__device__ __align__(256) __half g_w2g16[(size_t)HYP * OUT_F * IN_F];  // [h][o][i]
__device__ __align__(256) __half g_b2g16[OUT_F * IN_F];                // [o][i]
__device__ __align__(256) __half g_w2bT16[OUT_F * HYP];                // [o][k]
__device__ int g_flag[HYP];                                            // per-h W2g16 ready

// ---------------- PTX helpers (sm_80+ baseline ISA only) ----------------
__device__ __forceinline__ uint32_t smem_u32(const void* p) {
    uint32_t a;
    asm("{ .reg .u64 t; cvta.to.shared.u64 t, %1; cvt.u32.u64 %0, t; }" : "=r"(a) : "l"(p));
    return a;
}
#define CP16(dst, src) \
    asm volatile("cp.async.cg.shared.global [%0], [%1], 16;" :: "r"(dst), "l"(src) : "memory")
#define CP_COMMIT() asm volatile("cp.async.commit_group;" ::: "memory")
#define CP_WAIT(n)  asm volatile("cp.async.wait_group %0;" :: "n"(n) : "memory")

__device__ __forceinline__ void ldsm4(uint32_t* r, uint32_t addr) {
    asm volatile("ldmatrix.sync.aligned.m8n8.x4.shared.b16 {%0,%1,%2,%3}, [%4];"
        : "=r"(r[0]), "=r"(r[1]), "=r"(r[2]), "=r"(r[3]) : "r"(addr));
}
// d += A(16x16) * B(16x8)
__device__ __forceinline__ void mma_16816(float* d, const uint32_t* a, const uint32_t* b) {
    asm volatile(
        "mma.sync.aligned.m16n8k16.row.col.f32.f16.f16.f32 "
        "{%0,%1,%2,%3}, {%4,%5,%6,%7}, {%8,%9}, {%0,%1,%2,%3};"
        : "+f"(d[0]), "+f"(d[1]), "+f"(d[2]), "+f"(d[3])
        : "r"(a[0]), "r"(a[1]), "r"(a[2]), "r"(a[3]), "r"(b[0]), "r"(b[1]));
}

// ---------------- kernel 0: prep ----------------
// blocks 0..255: hidden activations (fp32, exact)
// blocks 256..319: flag reset + x16/b2g16/w2bT16/W2g[h<4] converts
__global__ __launch_bounds__(256) void prep_kernel(
    const float* __restrict__ x,
    const float* __restrict__ W1g, const float* __restrict__ b1g,
    const float* __restrict__ W1b, const float* __restrict__ b1b,
    const float* __restrict__ W2g, const float* __restrict__ b2g,
    const float* __restrict__ W2b)
{
    if (blockIdx.x < 256) {
        __shared__ __align__(16) float xs[16 * IN_F];
        const int b0 = blockIdx.x * 16;
        const int tid = threadIdx.x;
        const int h = tid & (HYP - 1);
        const int half = tid >> 7;

        for (int idx = tid; idx < 16 * IN_F / 4; idx += 256)
            ((float4*)xs)[idx] = ((const float4*)(x + (size_t)b0 * IN_F))[idx];
        __syncthreads();

        float accg[8], accb[8];
#pragma unroll
        for (int r = 0; r < 8; r++) { accg[r] = 0.f; accb[r] = 0.f; }
        for (int i = 0; i < IN_F; i++) {
            float wg = W1g[i * HYP + h];
            float wb = W1b[i * HYP + h];
#pragma unroll
            for (int r = 0; r < 8; r++) {
                float xv = xs[(half * 8 + r) * IN_F + i];
                accg[r] = fmaf(xv, wg, accg[r]);
                accb[r] = fmaf(xv, wb, accb[r]);
            }
        }
        float bg = b1g[h], bb = b1b[h];
#pragma unroll
        for (int r = 0; r < 8; r++) {
            int row = b0 + half * 8 + r;
            g_hgT[(size_t)h * B_SZ + row] = fmaxf(accg[r] + bg, 0.f);
            g_hb16[(size_t)row * HYP + h] = __float2half_rn(fmaxf(accb[r] + bb, 0.f));
        }
    } else {
        const int gtid = (blockIdx.x - 256) * 256 + threadIdx.x;  // 0..16383
        if (gtid < HYP) g_flag[gtid] = 0;                         // reset ready flags
        for (int t = gtid; t < OUT_F * HYP; t += 16384) {         // W2b transpose
            int o = t >> 7, k = t & 127;
            g_w2bT16[t] = __float2half_rn(W2b[k * OUT_F + o]);
        }
        // float4-granular converts: x (256K f4) + b2g (16K f4) + W2g h<4 (64K f4)
        const int NX = B_SZ * IN_F / 4;
        const int NB = NX + OUT_F * IN_F / 4;
        const int NW = NB + 4 * OUT_F * IN_F / 4;
        for (int i = gtid; i < NW; i += 16384) {
            const float4* src; __half* dst; int j;
            if (i < NX)      { src = (const float4*)x;   dst = g_x16;   j = i; }
            else if (i < NB) { src = (const float4*)b2g; dst = g_b2g16; j = i - NX; }
            else             { src = (const float4*)W2g; dst = g_w2g16; j = i - NB; }
            float4 v = src[j];
            __half2* d2 = (__half2*)(dst + j * 4);
            d2[0] = __floats2half2_rn(v.x, v.y);
            d2[1] = __floats2half2_rn(v.z, v.w);
        }
    }
}

// ---------------- kernel 1: mma.sync main + embedded W2g converter CTAs ----
// CTAs 0..127: compute (round-7 mainloop).  CTAs 128..147: convert W2g h>=4.
// smem: X 128x512B swz (64KB) | HB 128x256B swz (32KB) | B 3x 64x512B (96KB) | S 4x512B
#define X_OFF   0
#define HB_OFF  65536
#define B_OFF   98304
#define S_OFF   196608
#define SMEM_TOTAL 198656

__global__ __launch_bounds__(256, 1) void main_kernel(
    float* __restrict__ out, const float* __restrict__ b2b,
    const float* __restrict__ W2g)
{
    const int tid = threadIdx.x;

    // ---- converter CTAs: stream W2g fp32 -> fp16, publish per-h flags ----
    if (blockIdx.x >= 128) {
        const int c = blockIdx.x - 128;   // 0..19
        for (int h = 4 + c; h < HYP; h += 20) {
            const float4* src = (const float4*)(W2g + (size_t)h * OUT_F * IN_F);
            __half2* dst = (__half2*)(g_w2g16 + (size_t)h * OUT_F * IN_F);
#pragma unroll 4
            for (int i = tid; i < OUT_F * IN_F / 4; i += 256) {
                float4 v = src[i];
                dst[i * 2 + 0] = __floats2half2_rn(v.x, v.y);
                dst[i * 2 + 1] = __floats2half2_rn(v.z, v.w);
            }
            __syncthreads();
            if (tid == 0) {
                __threadfence();
                *((volatile int*)(g_flag + h)) = 1;
            }
        }
        return;
    }

    // ---- compute CTAs ----
    extern __shared__ __align__(1024) char smem[];
    const uint32_t sb = smem_u32(smem);
    const int lane = tid & 31;
    const int wid = tid >> 5;
    const int wm = wid & 3;      // warp M position (x32)
    const int wn = wid >> 2;     // warp N position (x32)
    const int b0 = (blockIdx.x & 31) * BM;
    const int o0 = (blockIdx.x >> 5) * BN;

    // B-tile (buffer hh%3) + hg scale (buffer hh&3) prefetch; one commit group always
    auto issueB = [&](int hh) {
        if (hh <= 129) {
            if (hh >= 4 && hh < 128) {      // wait until converter published plane hh
                volatile const int* fp = (volatile const int*)(g_flag + hh);
                while (*fp == 0) { __nanosleep(64); }
            }
            uint32_t dbuf = sb + B_OFF + (uint32_t)(hh % 3) * 32768;
            const __half* src; int nsh;
            if (hh < 128)       { src = g_w2g16 + (size_t)hh * OUT_F * IN_F + (size_t)o0 * IN_F; nsh = 5; }
            else if (hh == 128) { src = g_b2g16 + (size_t)o0 * IN_F; nsh = 5; }
            else                { src = g_w2bT16 + (size_t)o0 * HYP; nsh = 4; }
            int ldh = 1 << (nsh + 3);
            int msk = (1 << nsh) - 1;
            int tot = 64 << nsh;
            for (int idx = tid; idx < tot; idx += 256) {
                int row = idx >> nsh, k8 = idx & msk;
                CP16(dbuf + row * 512 + (uint32_t)((k8 ^ (row & 7)) << 4),
                     src + (size_t)row * ldh + k8 * 8);
            }
            if (hh < 128 && tid < 32)
                CP16(sb + S_OFF + (uint32_t)(hh & 3) * 512 + tid * 16,
                     g_hgT + (size_t)hh * B_SZ + b0 + tid * 4);
        }
        CP_COMMIT();
    };

    // ---- prologue: g0 = X + HB; g1 = B0 + S0; g2 = B1 + S1 ----
    for (int idx = tid; idx < 128 * 32; idx += 256) {
        int row = idx >> 5, k8 = idx & 31;
        CP16(sb + X_OFF + row * 512 + (uint32_t)((k8 ^ (row & 7)) << 4),
             g_x16 + (size_t)(b0 + row) * IN_F + k8 * 8);
    }
    for (int idx = tid; idx < 128 * 16; idx += 256) {
        int row = idx >> 4, k8 = idx & 15;
        CP16(sb + HB_OFF + row * 256 + (uint32_t)((k8 ^ (row & 7)) << 4),
             g_hb16 + (size_t)(b0 + row) * HYP + k8 * 8);
    }
    CP_COMMIT();
    issueB(0);
    issueB(1);

    // ---- per-thread fragment addressing ----
    const uint32_t a_row = (uint32_t)(wm * 32 + (lane & 15));
    const uint32_t a_sw  = (uint32_t)(lane & 7);
    const uint32_t a_hi  = (uint32_t)(lane >> 4);
    uint32_t b_off[4];
#pragma unroll
    for (int nn = 0; nn < 4; nn++)
        b_off[nn] = (uint32_t)(wn * 32 + nn * 8 + (lane & 7)) * 512;
    const uint32_t b_sw = (uint32_t)(lane & 7);
    const uint32_t b_hi = (uint32_t)(lane >> 3);

    float c[2][4][4];
    float p0[2][4][4], p1[2][4][4];
#pragma unroll
    for (int mf = 0; mf < 2; mf++)
#pragma unroll
        for (int nn = 0; nn < 4; nn++)
#pragma unroll
            for (int e = 0; e < 4; e++) {
                c[mf][nn][e] = 0.f; p0[mf][nn][e] = 0.f; p1[mf][nn][e] = 0.f;
            }

    const uint32_t xb  = sb + X_OFF;
    const uint32_t hbb = sb + HB_OFF;

    // one k32 step: 8 LDSM.x4 + 16 MMA into pc
    auto do_k32 = [&](uint32_t abase, uint32_t rs, uint32_t bbase, int k32,
                      float (&pc)[2][4][4]) {
        uint32_t Af[2][2][4];
#pragma unroll
        for (int mf = 0; mf < 2; mf++)
#pragma unroll
            for (int kr = 0; kr < 2; kr++) {
                uint32_t k8 = (uint32_t)(k32 * 4 + kr * 2) + a_hi;
                ldsm4(Af[mf][kr], abase + (a_row + (uint32_t)mf * 16) * rs + ((k8 ^ a_sw) << 4));
            }
        uint32_t Bf[4][4];
#pragma unroll
        for (int nn = 0; nn < 4; nn++) {
            uint32_t k8 = (uint32_t)(k32 * 4) + b_hi;
            ldsm4(Bf[nn], bbase + b_off[nn] + ((k8 ^ b_sw) << 4));
        }
#pragma unroll
        for (int mf = 0; mf < 2; mf++)
#pragma unroll
            for (int nn = 0; nn < 4; nn++) {
                mma_16816(pc[mf][nn], Af[mf][0], &Bf[nn][0]);
                mma_16816(pc[mf][nn], Af[mf][1], &Bf[nn][2]);
            }
    };

    // epilogue tile (mf,nn) of previous iteration: c += s*pp, pp = 0
    auto epi_tile = [&](int mf, int nn, float (&pp)[2][4][4], const float* s2) {
#pragma unroll
        for (int e = 0; e < 4; e++) {
            c[mf][nn][e] = fmaf(s2[mf * 2 + (e >> 1)], pp[mf][nn][e], c[mf][nn][e]);
            pp[mf][nn][e] = 0.f;
        }
    };

    // one h-iteration: compute h into pc, interleave epilogue of h-1 from pp
    auto iter = [&](int h, float (&pc)[2][4][4], float (&pp)[2][4][4]) {
        CP_WAIT(1);
        __syncthreads();
        float s2[4] = {1.f, 1.f, 1.f, 1.f};
        if (h >= 1 && h <= 128) {
            const float* ss = (const float*)(smem + S_OFF + (size_t)((h - 1) & 3) * 512);
#pragma unroll
            for (int mf = 0; mf < 2; mf++)
#pragma unroll
                for (int g = 0; g < 2; g++)
                    s2[mf * 2 + g] = ss[wm * 32 + mf * 16 + g * 8 + (lane >> 2)];
        }
        issueB(h + 2);
        uint32_t bbase = sb + B_OFF + (uint32_t)(h % 3) * 32768;
        if (h != 129) {
#pragma unroll
            for (int k32 = 0; k32 < 8; k32++) {
                do_k32(xb, 512u, bbase, k32, pc);
                if (h > 0) epi_tile(k32 >> 2, k32 & 3, pp, s2);
            }
        } else {
#pragma unroll
            for (int k32 = 0; k32 < 4; k32++) {
                do_k32(hbb, 256u, bbase, k32, pc);
                epi_tile(0, k32, pp, s2);
                epi_tile(1, k32, pp, s2);
            }
        }
    };

    // ---- mainloop: h<128 W2g[h] (scaled); 128 b2g (s=1); 129 hb@W2bT (s=1) ----
#pragma unroll 1
    for (int h = 0; h < 130; h += 2) {
        iter(h,     p0, p1);
        iter(h + 1, p1, p0);
    }
    // tail: epilogue of h=129 (in p1), s = 1
#pragma unroll
    for (int mf = 0; mf < 2; mf++)
#pragma unroll
        for (int nn = 0; nn < 4; nn++)
#pragma unroll
            for (int e = 0; e < 4; e++)
                c[mf][nn][e] += p1[mf][nn][e];

    // ---- store: out = C + b2b ----
    const int r_base = b0 + wm * 32 + (lane >> 2);
    const int c_base = o0 + wn * 32 + (lane & 3) * 2;
#pragma unroll
    for (int mf = 0; mf < 2; mf++)
#pragma unroll
        for (int nn = 0; nn < 4; nn++) {
            float2 bb2 = *(const float2*)(b2b + c_base + nn * 8);
#pragma unroll
            for (int g = 0; g < 2; g++) {
                int row = r_base + mf * 16 + g * 8;
                float2 v;
                v.x = c[mf][nn][g * 2 + 0] + bb2.x;
                v.y = c[mf][nn][g * 2 + 1] + bb2.y;
                *(float2*)(out + (size_t)row * OUT_F + c_base + nn * 8) = v;
            }
        }
}

// ---------------- launch ----------------
extern "C" void kernel_launch(void* const* d_in, const int* in_sizes, int n_in,
                              void* d_out, int out_size)
{
    const float* x   = (const float*)d_in[0];
    const float* W1g = (const float*)d_in[1];
    const float* b1g = (const float*)d_in[2];
    const float* W2g = (const float*)d_in[3];
    const float* b2g = (const float*)d_in[4];
    const float* W1b = (const float*)d_in[5];
    const float* b1b = (const float*)d_in[6];
    const float* W2b = (const float*)d_in[7];
    const float* b2b = (const float*)d_in[8];
    float* out = (float*)d_out;

    cudaFuncSetAttribute(main_kernel, cudaFuncAttributeMaxDynamicSharedMemorySize, SMEM_TOTAL);

    prep_kernel<<<320, 256>>>(x, W1g, b1g, W1b, b1b, W2g, b2g, W2b);
    main_kernel<<<148, 256, SMEM_TOTAL>>>(out, b2b, W2g);
}

// round 12
// speedup vs baseline: 1.1899x; 1.1899x over previous
#include <cuda_runtime.h>
#include <cuda_fp16.h>
#include <cstdint>

#define B_SZ  4096
#define IN_F  256
#define OUT_F 256
#define HYP   128
#define BM    128
#define BN    64

// ---------------- device scratch (allocation-free rule) ----------------
__device__ __align__(256) float  g_hgT[HYP * B_SZ];                    // [h][b] fp32
__device__ __align__(256) __half g_hb16[B_SZ * HYP];                   // [b][h]
__device__ __align__(256) __half g_x16[B_SZ * IN_F];                   // [b][i]
__device__ __align__(256) __half g_w2g16[(size_t)HYP * OUT_F * IN_F];  // [h][o][i]
__device__ __align__(256) __half g_b2g16[OUT_F * IN_F];                // [o][i]
__device__ __align__(256) __half g_w2bT16[OUT_F * HYP];                // [o][k]

// ---------------- PTX helpers (sm_80+ baseline ISA only) ----------------
__device__ __forceinline__ uint32_t smem_u32(const void* p) {
    uint32_t a;
    asm("{ .reg .u64 t; cvta.to.shared.u64 t, %1; cvt.u32.u64 %0, t; }" : "=r"(a) : "l"(p));
    return a;
}
#define CP16(dst, src) \
    asm volatile("cp.async.cg.shared.global [%0], [%1], 16;" :: "r"(dst), "l"(src) : "memory")
#define CP_COMMIT() asm volatile("cp.async.commit_group;" ::: "memory")
#define CP_WAIT(n)  asm volatile("cp.async.wait_group %0;" :: "n"(n) : "memory")

__device__ __forceinline__ void ldsm4(uint32_t* r, uint32_t addr) {
    asm volatile("ldmatrix.sync.aligned.m8n8.x4.shared.b16 {%0,%1,%2,%3}, [%4];"
        : "=r"(r[0]), "=r"(r[1]), "=r"(r[2]), "=r"(r[3]) : "r"(addr));
}
// d += A(16x16) * B(16x8)
__device__ __forceinline__ void mma_16816(float* d, const uint32_t* a, const uint32_t* b) {
    asm volatile(
        "mma.sync.aligned.m16n8k16.row.col.f32.f16.f16.f32 "
        "{%0,%1,%2,%3}, {%4,%5,%6,%7}, {%8,%9}, {%0,%1,%2,%3};"
        : "+f"(d[0]), "+f"(d[1]), "+f"(d[2]), "+f"(d[3])
        : "r"(a[0]), "r"(a[1]), "r"(a[2]), "r"(a[3]), "r"(b[0]), "r"(b[1]));
}

// ---------------- kernel 0: prep ----------------
// blocks 0..511:    hidden activations, 8 batch rows each (fp32, exact)
// blocks 512..1535: fp32 -> fp16 converts + W2b transpose (ILP-2 grid stride)
__global__ __launch_bounds__(256) void prep_kernel(
    const float* __restrict__ x,
    const float* __restrict__ W1g, const float* __restrict__ b1g,
    const float* __restrict__ W1b, const float* __restrict__ b1b,
    const float* __restrict__ W2g, const float* __restrict__ b2g,
    const float* __restrict__ W2b)
{
    if (blockIdx.x < 512) {
        // ---- hidden: hg/hb for 8 batch rows ----
        __shared__ __align__(16) float xs[8 * IN_F];
        const int b0 = blockIdx.x * 8;
        const int tid = threadIdx.x;
        const int h = tid & (HYP - 1);
        const int half = tid >> 7;   // rows half*4 .. half*4+3

        for (int idx = tid; idx < 8 * IN_F / 4; idx += 256)
            ((float4*)xs)[idx] = ((const float4*)(x + (size_t)b0 * IN_F))[idx];
        __syncthreads();

        float accg[4], accb[4];
#pragma unroll
        for (int r = 0; r < 4; r++) { accg[r] = 0.f; accb[r] = 0.f; }
#pragma unroll 4
        for (int i = 0; i < IN_F; i++) {
            float wg = W1g[i * HYP + h];
            float wb = W1b[i * HYP + h];
#pragma unroll
            for (int r = 0; r < 4; r++) {
                float xv = xs[(half * 4 + r) * IN_F + i];
                accg[r] = fmaf(xv, wg, accg[r]);
                accb[r] = fmaf(xv, wb, accb[r]);
            }
        }
        float bg = b1g[h], bb = b1b[h];
#pragma unroll
        for (int r = 0; r < 4; r++) {
            int row = b0 + half * 4 + r;
            g_hgT[(size_t)h * B_SZ + row] = fmaxf(accg[r] + bg, 0.f);
            g_hb16[(size_t)row * HYP + h] = __float2half_rn(fmaxf(accb[r] + bb, 0.f));
        }
    } else {
        const int gtid = (blockIdx.x - 512) * 256 + threadIdx.x;  // 0..262143
        if (gtid < OUT_F * HYP) {                                 // W2b transpose
            int o = gtid >> 7, k = gtid & 127;
            g_w2bT16[gtid] = __float2half_rn(W2b[k * OUT_F + o]);
        }
        // float4-granular converts, 2 independent elements per iteration (ILP)
        const int64_t N1 = (int64_t)HYP * OUT_F * IN_F / 4;       // W2g
        const int64_t N2 = N1 + (int64_t)OUT_F * IN_F / 4;        // b2g
        const int64_t N3 = N2 + (int64_t)B_SZ * IN_F / 4;         // x
        const int64_t stride = (int64_t)1024 * 256;
        auto cvt1 = [&](int64_t i) {
            const float4* src; __half* dst; int64_t j;
            if (i < N1)      { src = (const float4*)W2g; dst = g_w2g16; j = i; }
            else if (i < N2) { src = (const float4*)b2g; dst = g_b2g16; j = i - N1; }
            else             { src = (const float4*)x;   dst = g_x16;   j = i - N2; }
            float4 v = src[j];
            __half2* d2 = (__half2*)(dst + j * 4);
            d2[0] = __floats2half2_rn(v.x, v.y);
            d2[1] = __floats2half2_rn(v.z, v.w);
        };
        int64_t i = gtid;
        for (; i + stride < N3; i += 2 * stride) {   // two independent per iter
            cvt1(i);
            cvt1(i + stride);
        }
        if (i < N3) cvt1(i);
    }
}

// ---------------- kernel 1: mma.sync main (round-7 proven variant) ----------
// smem: X 128x512B swz (64KB) | HB 128x256B swz (32KB)
//       B 3x 64x512B (96KB) | S 4x 512B scale buffers
#define X_OFF   0
#define HB_OFF  65536
#define B_OFF   98304
#define S_OFF   196608
#define SMEM_TOTAL 198656

__global__ __launch_bounds__(256, 1) void main_kernel(
    float* __restrict__ out, const float* __restrict__ b2b)
{
    extern __shared__ __align__(1024) char smem[];
    const uint32_t sb = smem_u32(smem);
    const int tid = threadIdx.x;
    const int lane = tid & 31;
    const int wid = tid >> 5;
    const int wm = wid & 3;      // warp M position (x32)
    const int wn = wid >> 2;     // warp N position (x32)
    const int b0 = blockIdx.x * BM;
    const int o0 = blockIdx.y * BN;

    // B-tile (buffer hh%3) + hg scale (buffer hh&3) prefetch; one commit group always
    auto issueB = [&](int hh) {
        if (hh <= 129) {
            uint32_t dbuf = sb + B_OFF + (uint32_t)(hh % 3) * 32768;
            const __half* src; int nsh;
            if (hh < 128)       { src = g_w2g16 + (size_t)hh * OUT_F * IN_F + (size_t)o0 * IN_F; nsh = 5; }
            else if (hh == 128) { src = g_b2g16 + (size_t)o0 * IN_F; nsh = 5; }
            else                { src = g_w2bT16 + (size_t)o0 * HYP; nsh = 4; }
            int ldh = 1 << (nsh + 3);
            int msk = (1 << nsh) - 1;
            int tot = 64 << nsh;
            for (int idx = tid; idx < tot; idx += 256) {
                int row = idx >> nsh, k8 = idx & msk;
                CP16(dbuf + row * 512 + (uint32_t)((k8 ^ (row & 7)) << 4),
                     src + (size_t)row * ldh + k8 * 8);
            }
            if (hh < 128 && tid < 32)
                CP16(sb + S_OFF + (uint32_t)(hh & 3) * 512 + tid * 16,
                     g_hgT + (size_t)hh * B_SZ + b0 + tid * 4);
        }
        CP_COMMIT();
    };

    // ---- prologue: g0 = X + HB; g1 = B0 + S0; g2 = B1 + S1 ----
    for (int idx = tid; idx < 128 * 32; idx += 256) {
        int row = idx >> 5, k8 = idx & 31;
        CP16(sb + X_OFF + row * 512 + (uint32_t)((k8 ^ (row & 7)) << 4),
             g_x16 + (size_t)(b0 + row) * IN_F + k8 * 8);
    }
    for (int idx = tid; idx < 128 * 16; idx += 256) {
        int row = idx >> 4, k8 = idx & 15;
        CP16(sb + HB_OFF + row * 256 + (uint32_t)((k8 ^ (row & 7)) << 4),
             g_hb16 + (size_t)(b0 + row) * HYP + k8 * 8);
    }
    CP_COMMIT();
    issueB(0);
    issueB(1);

    // ---- per-thread fragment addressing ----
    const uint32_t a_row = (uint32_t)(wm * 32 + (lane & 15));
    const uint32_t a_sw  = (uint32_t)(lane & 7);
    const uint32_t a_hi  = (uint32_t)(lane >> 4);
    uint32_t b_off[4];
#pragma unroll
    for (int nn = 0; nn < 4; nn++)
        b_off[nn] = (uint32_t)(wn * 32 + nn * 8 + (lane & 7)) * 512;
    const uint32_t b_sw = (uint32_t)(lane & 7);
    const uint32_t b_hi = (uint32_t)(lane >> 3);

    float c[2][4][4];
    float p0[2][4][4], p1[2][4][4];
#pragma unroll
    for (int mf = 0; mf < 2; mf++)
#pragma unroll
        for (int nn = 0; nn < 4; nn++)
#pragma unroll
            for (int e = 0; e < 4; e++) {
                c[mf][nn][e] = 0.f; p0[mf][nn][e] = 0.f; p1[mf][nn][e] = 0.f;
            }

    const uint32_t xb  = sb + X_OFF;
    const uint32_t hbb = sb + HB_OFF;

    // one k32 step: 8 LDSM.x4 + 16 MMA into pc
    auto do_k32 = [&](uint32_t abase, uint32_t rs, uint32_t bbase, int k32,
                      float (&pc)[2][4][4]) {
        uint32_t Af[2][2][4];
#pragma unroll
        for (int mf = 0; mf < 2; mf++)
#pragma unroll
            for (int kr = 0; kr < 2; kr++) {
                uint32_t k8 = (uint32_t)(k32 * 4 + kr * 2) + a_hi;
                ldsm4(Af[mf][kr], abase + (a_row + (uint32_t)mf * 16) * rs + ((k8 ^ a_sw) << 4));
            }
        uint32_t Bf[4][4];
#pragma unroll
        for (int nn = 0; nn < 4; nn++) {
            uint32_t k8 = (uint32_t)(k32 * 4) + b_hi;
            ldsm4(Bf[nn], bbase + b_off[nn] + ((k8 ^ b_sw) << 4));
        }
#pragma unroll
        for (int mf = 0; mf < 2; mf++)
#pragma unroll
            for (int nn = 0; nn < 4; nn++) {
                mma_16816(pc[mf][nn], Af[mf][0], &Bf[nn][0]);
                mma_16816(pc[mf][nn], Af[mf][1], &Bf[nn][2]);
            }
    };

    // epilogue tile (mf,nn) of previous iteration: c += s*pp, pp = 0
    auto epi_tile = [&](int mf, int nn, float (&pp)[2][4][4], const float* s2) {
#pragma unroll
        for (int e = 0; e < 4; e++) {
            c[mf][nn][e] = fmaf(s2[mf * 2 + (e >> 1)], pp[mf][nn][e], c[mf][nn][e]);
            pp[mf][nn][e] = 0.f;
        }
    };

    // one h-iteration: compute h into pc, interleave epilogue of h-1 from pp
    auto iter = [&](int h, float (&pc)[2][4][4], float (&pp)[2][4][4]) {
        CP_WAIT(1);
        __syncthreads();
        float s2[4] = {1.f, 1.f, 1.f, 1.f};
        if (h >= 1 && h <= 128) {
            const float* ss = (const float*)(smem + S_OFF + (size_t)((h - 1) & 3) * 512);
#pragma unroll
            for (int mf = 0; mf < 2; mf++)
#pragma unroll
                for (int g = 0; g < 2; g++)
                    s2[mf * 2 + g] = ss[wm * 32 + mf * 16 + g * 8 + (lane >> 2)];
        }
        issueB(h + 2);
        uint32_t bbase = sb + B_OFF + (uint32_t)(h % 3) * 32768;
        if (h != 129) {
#pragma unroll
            for (int k32 = 0; k32 < 8; k32++) {
                do_k32(xb, 512u, bbase, k32, pc);
                if (h > 0) epi_tile(k32 >> 2, k32 & 3, pp, s2);
            }
        } else {
#pragma unroll
            for (int k32 = 0; k32 < 4; k32++) {
                do_k32(hbb, 256u, bbase, k32, pc);
                epi_tile(0, k32, pp, s2);
                epi_tile(1, k32, pp, s2);
            }
        }
    };

    // ---- mainloop: h<128 W2g[h] (scaled); 128 b2g (s=1); 129 hb@W2bT (s=1) ----
#pragma unroll 1
    for (int h = 0; h < 130; h += 2) {
        iter(h,     p0, p1);
        iter(h + 1, p1, p0);
    }
    // tail: epilogue of h=129 (in p1), s = 1
#pragma unroll
    for (int mf = 0; mf < 2; mf++)
#pragma unroll
        for (int nn = 0; nn < 4; nn++)
#pragma unroll
            for (int e = 0; e < 4; e++)
                c[mf][nn][e] += p1[mf][nn][e];

    // ---- store: out = C + b2b ----
    const int r_base = b0 + wm * 32 + (lane >> 2);
    const int c_base = o0 + wn * 32 + (lane & 3) * 2;
#pragma unroll
    for (int mf = 0; mf < 2; mf++)
#pragma unroll
        for (int nn = 0; nn < 4; nn++) {
            float2 bb2 = *(const float2*)(b2b + c_base + nn * 8);
#pragma unroll
            for (int g = 0; g < 2; g++) {
                int row = r_base + mf * 16 + g * 8;
                float2 v;
                v.x = c[mf][nn][g * 2 + 0] + bb2.x;
                v.y = c[mf][nn][g * 2 + 1] + bb2.y;
                *(float2*)(out + (size_t)row * OUT_F + c_base + nn * 8) = v;
            }
        }
}

// ---------------- launch ----------------
extern "C" void kernel_launch(void* const* d_in, const int* in_sizes, int n_in,
                              void* d_out, int out_size)
{
    const float* x   = (const float*)d_in[0];
    const float* W1g = (const float*)d_in[1];
    const float* b1g = (const float*)d_in[2];
    const float* W2g = (const float*)d_in[3];
    const float* b2g = (const float*)d_in[4];
    const float* W1b = (const float*)d_in[5];
    const float* b1b = (const float*)d_in[6];
    const float* W2b = (const float*)d_in[7];
    const float* b2b = (const float*)d_in[8];
    float* out = (float*)d_out;

    cudaFuncSetAttribute(main_kernel, cudaFuncAttributeMaxDynamicSharedMemorySize, SMEM_TOTAL);

    prep_kernel<<<1536, 256>>>(x, W1g, b1g, W1b, b1b, W2g, b2g, W2b);
    dim3 grid(B_SZ / BM, OUT_F / BN);
    main_kernel<<<grid, 256, SMEM_TOTAL>>>(out, b2b);
}